// round 8
// baseline (speedup 1.0000x reference)
#include <cuda_runtime.h>
#include <cstdint>

// ---------------------------------------------------------------------------
// out = ((x @ (w1_q*s1)) @ (w2_q*s2)) per expert.  E=8, T=4096, H=2048.
// Exact 16-bit activation split (hi,lo int8 planes).
// ALL-DP4A GEMM: measured on sm_103a, legacy IMMA (298 MAC/cyc/SM) and dp4a
// (4.16 instr/cyc/SM = 532 MAC/cyc/SM) SERIALIZE on a shared resource, and
// dp4a is 1.8x cheaper per MAC -> do everything with dp4a.
//   warps 0-7  : hi plane, 32x64 tiles
//   warps 8-15 : lo plane, same tiles
// out = (256*acc_hi + acc_lo) * s_row * wscale_col.
// ---------------------------------------------------------------------------

#define EE 8
#define TT 4096
#define HH 2048

#define BM 128
#define BN 128
#define BK 128
#define NKIT (HH / BK)          // 16
#define PLANE 16384             // one 128x128 s8 tile
#define STAGE (3 * PLANE)       // A_hi + A_lo + B
#define NSTAGE 4
#define DYNSMEM (NSTAGE * STAGE)  // 196608 B
#define XPITCH 132              // padded int32 pitch for epilogue exchange

// -------------------- scratch --------------------------------------------
__device__ int8_t g_w1t[(size_t)EE * HH * HH];   // w1^T int8 [E][n][k]
__device__ int8_t g_w2t[(size_t)EE * HH * HH];   // w2^T int8 [E][n][k]
__device__ int8_t g_ahi[(size_t)EE * TT * HH];   // activation hi bytes
__device__ int8_t g_alo[(size_t)EE * TT * HH];   // activation lo bytes
__device__ float  g_rs [(size_t)EE * TT];        // per-row dequant scale
__device__ float  g_h  [(size_t)EE * TT * HH];   // layer-1 output fp32

// -------------------- helpers --------------------------------------------
__device__ __forceinline__ uint32_t smem_u32(const void* p) {
    uint32_t a;
    asm("{ .reg .u64 t; cvta.to.shared.u64 t, %1; cvt.u32.u64 %0, t; }"
        : "=r"(a) : "l"(p));
    return a;
}

#define CP_ASYNC16(dst, src) \
    asm volatile("cp.async.cg.shared.global [%0], [%1], 16;" \
                 :: "r"(dst), "l"(src) : "memory")
#define CP_COMMIT() asm volatile("cp.async.commit_group;" ::: "memory")
#define CP_WAIT2()  asm volatile("cp.async.wait_group 2;" ::: "memory")
#define CP_WAIT0()  asm volatile("cp.async.wait_group 0;" ::: "memory")

__device__ __forceinline__ int dp4a_(int a, int b, int c) {
    int d;
    asm("dp4a.s32.s32 %0, %1, %2, %3;" : "=r"(d) : "r"(a), "r"(b), "r"(c));
    return d;
}

// -------------------- weight convert + transpose --------------------------
__global__ void convw_kernel(const int* __restrict__ W,
                             int8_t* __restrict__ O) {
    __shared__ int8_t tile[32][33];
    const int e  = blockIdx.z;
    const int n0 = blockIdx.x * 32;
    const int k0 = blockIdx.y * 32;
    const int tx = threadIdx.x, ty = threadIdx.y;

    const int* src = W + ((size_t)e * HH + k0) * HH + n0;
#pragma unroll
    for (int r = 0; r < 4; r++) {
        tile[ty + r * 8][tx] = (int8_t)src[(size_t)(ty + r * 8) * HH + tx];
    }
    __syncthreads();
    const int t  = ty * 32 + tx;
    const int nr = t >> 3;
    const int c4 = (t & 7) * 4;
    uint32_t p = (uint32_t)(uint8_t)tile[c4 + 0][nr]
               | ((uint32_t)(uint8_t)tile[c4 + 1][nr] << 8)
               | ((uint32_t)(uint8_t)tile[c4 + 2][nr] << 16)
               | ((uint32_t)(uint8_t)tile[c4 + 3][nr] << 24);
    *(uint32_t*)(O + ((size_t)e * HH + n0 + nr) * HH + k0 + c4) = p;
}

// -------------------- activation quantize (16-bit split) -------------------
__global__ void quant_kernel(const float* __restrict__ X,
                             int8_t* __restrict__ Qh,
                             int8_t* __restrict__ Ql,
                             float* __restrict__ RS) {
    const int row = blockIdx.x;
    const float* x = X + (size_t)row * HH;
    const int tid = threadIdx.x;

    const float4 v0 = ((const float4*)x)[tid];
    const float4 v1 = ((const float4*)x)[tid + 256];

    float m = fabsf(v0.x);
    m = fmaxf(m, fabsf(v0.y)); m = fmaxf(m, fabsf(v0.z));
    m = fmaxf(m, fabsf(v0.w)); m = fmaxf(m, fabsf(v1.x));
    m = fmaxf(m, fabsf(v1.y)); m = fmaxf(m, fabsf(v1.z));
    m = fmaxf(m, fabsf(v1.w));
#pragma unroll
    for (int o = 16; o; o >>= 1)
        m = fmaxf(m, __shfl_xor_sync(0xFFFFFFFFu, m, o));
    __shared__ float wr[8];
    if ((tid & 31) == 0) wr[tid >> 5] = m;
    __syncthreads();
    float mx = wr[0];
#pragma unroll
    for (int j = 1; j < 8; j++) mx = fmaxf(mx, wr[j]);
    mx = fmaxf(mx, 1e-20f);
    const float inv = 32600.0f / mx;

    uint32_t* ph = (uint32_t*)(Qh + (size_t)row * HH);
    uint32_t* pl = (uint32_t*)(Ql + (size_t)row * HH);

    {
        const int q0 = __float2int_rn(v0.x * inv);
        const int q1 = __float2int_rn(v0.y * inv);
        const int q2 = __float2int_rn(v0.z * inv);
        const int q3 = __float2int_rn(v0.w * inv);
        const int h0 = (q0 + 128) >> 8, h1 = (q1 + 128) >> 8;
        const int h2 = (q2 + 128) >> 8, h3 = (q3 + 128) >> 8;
        const int l0 = q0 - (h0 << 8), l1 = q1 - (h1 << 8);
        const int l2 = q2 - (h2 << 8), l3 = q3 - (h3 << 8);
        ph[tid] = (h0 & 255) | ((h1 & 255) << 8) | ((h2 & 255) << 16)
                | ((uint32_t)(h3 & 255) << 24);
        pl[tid] = (l0 & 255) | ((l1 & 255) << 8) | ((l2 & 255) << 16)
                | ((uint32_t)(l3 & 255) << 24);
    }
    {
        const int q0 = __float2int_rn(v1.x * inv);
        const int q1 = __float2int_rn(v1.y * inv);
        const int q2 = __float2int_rn(v1.z * inv);
        const int q3 = __float2int_rn(v1.w * inv);
        const int h0 = (q0 + 128) >> 8, h1 = (q1 + 128) >> 8;
        const int h2 = (q2 + 128) >> 8, h3 = (q3 + 128) >> 8;
        const int l0 = q0 - (h0 << 8), l1 = q1 - (h1 << 8);
        const int l2 = q2 - (h2 << 8), l3 = q3 - (h3 << 8);
        ph[tid + 256] = (h0 & 255) | ((h1 & 255) << 8) | ((h2 & 255) << 16)
                      | ((uint32_t)(h3 & 255) << 24);
        pl[tid + 256] = (l0 & 255) | ((l1 & 255) << 8) | ((l2 & 255) << 16)
                      | ((uint32_t)(l3 & 255) << 24);
    }
    if (tid == 0) RS[row] = mx / 32600.0f;
}

// -------------------- all-dp4a GEMM ----------------------------------------
__global__ void __launch_bounds__(512, 1)
dp4a_gemm(const int8_t* __restrict__ Ah, const int8_t* __restrict__ Al,
          const float* __restrict__ rs, const int8_t* __restrict__ Bt,
          const float* __restrict__ cs, float* __restrict__ C) {
    extern __shared__ char sm[];
    const uint32_t sbase = smem_u32(sm);
    const int tid = threadIdx.x;
    const int lane = tid & 31, wid = tid >> 5;

    const int e  = blockIdx.z;
    const int m0 = blockIdx.y * BM;
    const int n0 = blockIdx.x * BN;

    const int8_t* gA = Ah + ((size_t)e * TT + m0) * HH;
    const int8_t* gL = Al + ((size_t)e * TT + m0) * HH;
    const int8_t* gB = Bt + ((size_t)e * HH + n0) * HH;

    // loader addressing (all 512 threads, 2x16B per plane)
    const int lr = tid >> 3;
    const int lc = (tid & 7) << 4;
    const uint32_t sw0 =
        (uint32_t)(lr * 128 + ((((lc >> 4) ^ lr) & 7) << 4));
    const uint32_t sw1 =
        (uint32_t)((lr + 64) * 128 + ((((lc >> 4) ^ (lr + 64)) & 7) << 4));
    const size_t go0 = (size_t)lr * HH + lc;
    const size_t go1 = (size_t)(lr + 64) * HH + lc;

    // tile config: warp (wid&7) -> 32x64 outputs; wid<8 hi plane, else lo
    const int dwid = wid & 7;
    const int wtr = dwid >> 1;          // 0..3 -> rows wtr*32
    const int wtc = dwid & 1;           // 0..1 -> cols wtc*64
    const int lg = lane & 3;            // row class (mod 4)
    const int lh = lane >> 2;           // col class (mod 8)
    const uint32_t dpA0 = (uint32_t)((wtr * 32 + lg) * 128);
    const uint32_t dpB0 = (uint32_t)((wtc * 64 + lh) * 128);
    const int planeOff = (wid < 8) ? 0 : PLANE;

    int acc[8][8];
#pragma unroll
    for (int a = 0; a < 8; a++)
#pragma unroll
        for (int b = 0; b < 8; b++) acc[a][b] = 0;

    // prologue: fill stages 0..3 with k-iters 0..3
#pragma unroll
    for (int p = 0; p < NSTAGE; p++) {
        const uint32_t st = sbase + p * STAGE;
        const size_t k0 = (size_t)p * BK;
        CP_ASYNC16(st + sw0,             gA + go0 + k0);
        CP_ASYNC16(st + sw1,             gA + go1 + k0);
        CP_ASYNC16(st + PLANE + sw0,     gL + go0 + k0);
        CP_ASYNC16(st + PLANE + sw1,     gL + go1 + k0);
        CP_ASYNC16(st + 2 * PLANE + sw0, gB + go0 + k0);
        CP_ASYNC16(st + 2 * PLANE + sw1, gB + go1 + k0);
        CP_COMMIT();
    }

    // windows: consume stage pair, 2 k-iters per barrier window
#pragma unroll 1
    for (int w = 0; w < NKIT / 2; w++) {
        if (w < NKIT / 2 - 1) { CP_WAIT2(); } else { CP_WAIT0(); }
        __syncthreads();
        const int sp = (w & 1) * 2;     // stage pair base

#pragma unroll
        for (int t = 0; t < 2; t++) {
            const char* stP = sm + (sp + t) * STAGE + planeOff;
            const char* stB = sm + (sp + t) * STAGE + 2 * PLANE;
#pragma unroll 2
            for (int kb = 0; kb < BK; kb += 16) {
                const uint32_t cA0 =
                    (uint32_t)(((((kb >> 4)) ^ lg) & 7) << 4);
                const uint32_t cA1 = cA0 ^ 64u;
                const uint32_t cB =
                    (uint32_t)(((((kb >> 4)) ^ lh) & 7) << 4);
                int4 bv[8];
#pragma unroll
                for (int j2 = 0; j2 < 8; j2++) {
                    bv[j2] = *(const int4*)(stB + dpB0
                                            + (uint32_t)(j2 * 1024) + cB);
                }
#pragma unroll
                for (int j = 0; j < 8; j++) {
                    const int4 a = *(const int4*)(stP + dpA0
                                     + (uint32_t)(j * 512)
                                     + ((j & 1) ? cA1 : cA0));
#pragma unroll
                    for (int j2 = 0; j2 < 8; j2++) {
                        acc[j][j2] =
                            dp4a_(a.x, bv[j2].x,
                            dp4a_(a.y, bv[j2].y,
                            dp4a_(a.z, bv[j2].z,
                            dp4a_(a.w, bv[j2].w, acc[j][j2]))));
                    }
                }
            }
        }
        __syncthreads();

        // refill the consumed pair with k-iters 2w+4, 2w+5
        if (w < NKIT / 2 - 2) {
#pragma unroll
            for (int t = 0; t < 2; t++) {
                const uint32_t st = sbase + (sp + t) * STAGE;
                const size_t k0 = (size_t)(2 * w + 4 + t) * BK;
                CP_ASYNC16(st + sw0,             gA + go0 + k0);
                CP_ASYNC16(st + sw1,             gA + go1 + k0);
                CP_ASYNC16(st + PLANE + sw0,     gL + go0 + k0);
                CP_ASYNC16(st + PLANE + sw1,     gL + go1 + k0);
                CP_ASYNC16(st + 2 * PLANE + sw0, gB + go0 + k0);
                CP_ASYNC16(st + 2 * PLANE + sw1, gB + go1 + k0);
                CP_COMMIT();
            }
        }
    }

    // ---------------- epilogue ----------------
    __syncthreads();

    // exchange both acc planes through padded smem
    int* xch_hi = (int*)sm;                          // 128 x XPITCH
    int* xch_lo = xch_hi + 128 * XPITCH;             // 128 x XPITCH
    int* xch = (wid < 8) ? xch_hi : xch_lo;
#pragma unroll
    for (int j = 0; j < 8; j++)
#pragma unroll
        for (int j2 = 0; j2 < 8; j2++) {
            const int r = wtr * 32 + lg + 4 * j;
            const int c = wtc * 64 + lh + 8 * j2;
            xch[r * XPITCH + c] = acc[j][j2];
        }
    __syncthreads();

    // combine + scale + coalesced store: thread -> (row, 32-col slab)
    {
        const int r  = tid >> 2;               // 0..127
        const int c0 = (tid & 3) * 32;         // 0,32,64,96
        const float sr = rs[(size_t)e * TT + m0 + r];
        const float* csp = cs + (size_t)e * HH + n0;
        float* Crow = C + ((size_t)e * TT + m0 + r) * HH + n0;
        const int* ph = xch_hi + r * XPITCH + c0;
        const int* pl = xch_lo + r * XPITCH + c0;
#pragma unroll
        for (int c = 0; c < 32; c += 4) {
            float4 o;
            o.x = fmaf(256.0f, (float)ph[c + 0], (float)pl[c + 0])
                  * (sr * csp[c0 + c + 0]);
            o.y = fmaf(256.0f, (float)ph[c + 1], (float)pl[c + 1])
                  * (sr * csp[c0 + c + 1]);
            o.z = fmaf(256.0f, (float)ph[c + 2], (float)pl[c + 2])
                  * (sr * csp[c0 + c + 2]);
            o.w = fmaf(256.0f, (float)ph[c + 3], (float)pl[c + 3])
                  * (sr * csp[c0 + c + 3]);
            *(float4*)(Crow + c0 + c) = o;
        }
    }
}

// -------------------- launcher --------------------------------------------
extern "C" void kernel_launch(void* const* d_in, const int* in_sizes, int n_in,
                              void* d_out, int out_size) {
    const float* x   = (const float*)d_in[0];
    const int*   w1q = (const int*)d_in[1];
    const float* w1s = (const float*)d_in[2];
    const int*   w2q = (const int*)d_in[3];
    const float* w2s = (const float*)d_in[4];
    float*       out = (float*)d_out;

    void *pw1t, *pw2t, *pahi, *palo, *prs, *ph;
    cudaGetSymbolAddress(&pw1t, g_w1t);
    cudaGetSymbolAddress(&pw2t, g_w2t);
    cudaGetSymbolAddress(&pahi, g_ahi);
    cudaGetSymbolAddress(&palo, g_alo);
    cudaGetSymbolAddress(&prs,  g_rs);
    cudaGetSymbolAddress(&ph,   g_h);

    dim3 cb(32, 8), cg(HH / 32, HH / 32, EE);
    convw_kernel<<<cg, cb>>>(w1q, (int8_t*)pw1t);
    convw_kernel<<<cg, cb>>>(w2q, (int8_t*)pw2t);

    quant_kernel<<<EE * TT, 256>>>(x, (int8_t*)pahi, (int8_t*)palo,
                                   (float*)prs);

    cudaFuncSetAttribute(dp4a_gemm,
                         cudaFuncAttributeMaxDynamicSharedMemorySize, DYNSMEM);
    dim3 gg(HH / BN, TT / BM, EE);   // (16, 32, 8)

    dp4a_gemm<<<gg, 512, DYNSMEM>>>((const int8_t*)pahi, (const int8_t*)palo,
                                    (const float*)prs, (const int8_t*)pw1t,
                                    w1s, (float*)ph);

    quant_kernel<<<EE * TT, 256>>>((const float*)ph, (int8_t*)pahi,
                                   (int8_t*)palo, (float*)prs);

    dp4a_gemm<<<gg, 512, DYNSMEM>>>((const int8_t*)pahi, (const int8_t*)palo,
                                    (const float*)prs, (const int8_t*)pw2t,
                                    w2s, out);
}

// round 9
// speedup vs baseline: 1.4074x; 1.4074x over previous
#include <cuda_runtime.h>
#include <cstdint>

// ---------------------------------------------------------------------------
// out = ((x @ (w1_q*s1)) @ (w2_q*s2)) per expert.  E=8, T=4096, H=2048.
// Exact 16-bit activation split (hi,lo int8 planes).
// R5 compute (warps 0-7 IMMA hi / warps 8-15 DP4A lo) + BULK-COPY loader:
// all operands pre-tiled & pre-swizzled in gmem as contiguous 16KB tiles, so
// each k-iter needs just 3 cp.async.bulk (1 thread) instead of 3072 LDGSTS
// (512 threads) -> removes ~12k issue-cycles per window of loader overhead.
// out = (256*acc_hi + acc_lo) * s_row * wscale_col.
// ---------------------------------------------------------------------------

#define EE 8
#define TT 4096
#define HH 2048

#define BM 128
#define BN 128
#define BK 128
#define NKIT (HH / BK)          // 16
#define PLANE 16384             // one 128x128 s8 tile
#define STAGE (3 * PLANE)       // A_hi + A_lo + B  (49152 B)
#define NSTAGE 4
#define DYNSMEM (NSTAGE * STAGE)  // 196608 B

// -------------------- scratch (tiled, pre-swizzled) ------------------------
// weights: [e][nb(16)][kb(16)][16384]   activations: [e][mb(32)][kb(16)][16384]
__device__ int8_t g_w1t[(size_t)EE * HH * HH];
__device__ int8_t g_w2t[(size_t)EE * HH * HH];
__device__ int8_t g_ahi[(size_t)EE * TT * HH];
__device__ int8_t g_alo[(size_t)EE * TT * HH];
__device__ float  g_rs [(size_t)EE * TT];
__device__ float  g_h  [(size_t)EE * TT * HH];   // layer-1 output fp32 (row-major)

// -------------------- helpers --------------------------------------------
__device__ __forceinline__ uint32_t smem_u32(const void* p) {
    uint32_t a;
    asm("{ .reg .u64 t; cvta.to.shared.u64 t, %1; cvt.u32.u64 %0, t; }"
        : "=r"(a) : "l"(p));
    return a;
}

#define MBARRIER_INIT(mbar, cnt) \
    asm volatile("mbarrier.init.shared.b64 [%0], %1;" \
                 :: "r"((uint32_t)(mbar)), "r"((uint32_t)(cnt)) : "memory")
#define MBARRIER_EXPECT_TX(mbar, tx) \
    asm volatile("mbarrier.arrive.expect_tx.shared.b64 _, [%0], %1;" \
                 :: "r"((uint32_t)(mbar)), "r"((uint32_t)(tx)) : "memory")

#define MBARRIER_WAIT_PARITY(mbar, par) do {                                   \
    uint32_t _m = (uint32_t)(mbar);                                            \
    uint32_t _p = (uint32_t)(par);                                             \
    uint32_t _done;                                                            \
    asm volatile("{\n\t.reg .pred p;\n\t"                                      \
        "mbarrier.try_wait.parity.shared.b64 p, [%1], %2;\n\t"                 \
        "selp.b32 %0, 1, 0, p;\n\t}"                                           \
        : "=r"(_done) : "r"(_m), "r"(_p) : "memory");                          \
    if (!_done) {                                                              \
        asm volatile("{\n\t.reg .pred P1;\n\t"                                 \
            "WL_%=:\n\t"                                                       \
            "mbarrier.try_wait.parity.shared.b64 P1, [%0], %1;\n\t"            \
            "@P1 bra.uni WD_%=;\n\t"                                           \
            "bra.uni WL_%=;\n\t"                                               \
            "WD_%=:\n\t}"                                                      \
            :: "r"(_m), "r"(_p) : "memory");                                   \
    }                                                                          \
} while (0)

#define CP_BULK(dst, src, nbytes, mbar) \
    asm volatile( \
        "cp.async.bulk.shared::cluster.global.mbarrier::complete_tx::bytes " \
        "[%0], [%1], %2, [%3];" \
        :: "r"((uint32_t)(dst)), "l"(src), "r"((uint32_t)(nbytes)), \
           "r"((uint32_t)(mbar)) : "memory")

__device__ __forceinline__ void imma(int* d, const uint32_t* a,
                                     const uint32_t* b) {
    asm volatile(
        "mma.sync.aligned.m16n8k32.row.col.s32.s8.s8.s32 "
        "{%0,%1,%2,%3},{%4,%5,%6,%7},{%8,%9},{%0,%1,%2,%3};"
        : "+r"(d[0]), "+r"(d[1]), "+r"(d[2]), "+r"(d[3])
        : "r"(a[0]), "r"(a[1]), "r"(a[2]), "r"(a[3]),
          "r"(b[0]), "r"(b[1]));
}

__device__ __forceinline__ int dp4a_(int a, int b, int c) {
    int d;
    asm("dp4a.s32.s32 %0, %1, %2, %3;" : "=r"(d) : "r"(a), "r"(b), "r"(c));
    return d;
}

// -------------------- weight convert + transpose + tile + swizzle ----------
// W int32 [E][k][n] -> tiles [e][nb][kb][128x128] int8, chunk-swizzled
__global__ void convw_kernel(const int* __restrict__ W,
                             int8_t* __restrict__ O) {
    __shared__ int8_t tile[32][33];
    const int e  = blockIdx.z;
    const int n0 = blockIdx.x * 32;
    const int k0 = blockIdx.y * 32;
    const int tx = threadIdx.x, ty = threadIdx.y;

    const int* src = W + ((size_t)e * HH + k0) * HH + n0;
#pragma unroll
    for (int r = 0; r < 4; r++) {
        tile[ty + r * 8][tx] = (int8_t)src[(size_t)(ty + r * 8) * HH + tx];
    }
    __syncthreads();
    const int t  = ty * 32 + tx;
    const int nr = t >> 3;              // 0..31
    const int c4 = (t & 7) * 4;         // 0..28
    uint32_t p = (uint32_t)(uint8_t)tile[c4 + 0][nr]
               | ((uint32_t)(uint8_t)tile[c4 + 1][nr] << 8)
               | ((uint32_t)(uint8_t)tile[c4 + 2][nr] << 16)
               | ((uint32_t)(uint8_t)tile[c4 + 3][nr] << 24);
    const int ng = n0 + nr;
    const int nb = ng >> 7, rowT = ng & 127;
    const int kin = (k0 & 127) + c4;
    const int ch  = kin >> 4;
    const uint32_t sw = (uint32_t)(((ch ^ (rowT & 7)) & 7) << 4) + (kin & 15);
    int8_t* dst = O + (((size_t)(e * 16 + nb) * 16 + (k0 >> 7)) << 14)
                    + rowT * 128 + sw;
    *(uint32_t*)dst = p;
}

// -------------------- activation quantize (tiled + swizzled output) --------
// X fp32 row-major [rows][H]; Qh/Ql tiled [e][mb][kb][16384]; RS per-row
__global__ void quant_kernel(const float* __restrict__ X,
                             int8_t* __restrict__ Qh,
                             int8_t* __restrict__ Ql,
                             float* __restrict__ RS) {
    const int row = blockIdx.x;          // 0 .. EE*TT-1
    const float* x = X + (size_t)row * HH;
    const int t = threadIdx.x;           // 0..127

    float4 v[4];
#pragma unroll
    for (int j = 0; j < 4; j++) v[j] = ((const float4*)x)[t * 4 + j];

    float m = 0.0f;
#pragma unroll
    for (int j = 0; j < 4; j++) {
        m = fmaxf(m, fabsf(v[j].x)); m = fmaxf(m, fabsf(v[j].y));
        m = fmaxf(m, fabsf(v[j].z)); m = fmaxf(m, fabsf(v[j].w));
    }
#pragma unroll
    for (int o = 16; o; o >>= 1)
        m = fmaxf(m, __shfl_xor_sync(0xFFFFFFFFu, m, o));
    __shared__ float wr[4];
    if ((t & 31) == 0) wr[t >> 5] = m;
    __syncthreads();
    float mx = fmaxf(fmaxf(wr[0], wr[1]), fmaxf(wr[2], wr[3]));
    mx = fmaxf(mx, 1e-20f);
    const float inv = 32600.0f / mx;

    uint32_t hw[4], lw[4];
#pragma unroll
    for (int j = 0; j < 4; j++) {
        const int q0 = __float2int_rn(v[j].x * inv);
        const int q1 = __float2int_rn(v[j].y * inv);
        const int q2 = __float2int_rn(v[j].z * inv);
        const int q3 = __float2int_rn(v[j].w * inv);
        const int h0 = (q0 + 128) >> 8, h1 = (q1 + 128) >> 8;
        const int h2 = (q2 + 128) >> 8, h3 = (q3 + 128) >> 8;
        const int l0 = q0 - (h0 << 8), l1 = q1 - (h1 << 8);
        const int l2 = q2 - (h2 << 8), l3 = q3 - (h3 << 8);
        hw[j] = (h0 & 255) | ((h1 & 255) << 8) | ((h2 & 255) << 16)
              | ((uint32_t)(h3 & 255) << 24);
        lw[j] = (l0 & 255) | ((l1 & 255) << 8) | ((l2 & 255) << 16)
              | ((uint32_t)(l3 & 255) << 24);
    }

    const int e  = row >> 12;            // /TT
    const int mm = row & 4095;
    const int kb = t >> 3;               // 0..15
    const int ch = t & 7;                // chunk in tile
    const int rowT = mm & 127;
    const uint32_t sw = (uint32_t)(((ch ^ (rowT & 7)) & 7) << 4);
    const size_t base = (((size_t)(e * 32 + (mm >> 7)) * 16 + kb) << 14)
                      + rowT * 128 + sw;
    *(int4*)(Qh + base) = make_int4(hw[0], hw[1], hw[2], hw[3]);
    *(int4*)(Ql + base) = make_int4(lw[0], lw[1], lw[2], lw[3]);
    if (t == 0) RS[row] = mx / 32600.0f;
}

// -------------------- GEMM: bulk-copy pipeline + IMMA/DP4A split -----------
__global__ void __launch_bounds__(512, 1)
imma_gemm(const int8_t* __restrict__ Ah, const int8_t* __restrict__ Al,
          const float* __restrict__ rs, const int8_t* __restrict__ Bt,
          const float* __restrict__ cs, float* __restrict__ C) {
    extern __shared__ __align__(128) char sm[];
    __shared__ __align__(8) uint64_t mbar_s[NSTAGE];
    const uint32_t sbase = smem_u32(sm);
    const uint32_t mb0 = smem_u32(mbar_s);
    const int tid = threadIdx.x;
    const int lane = tid & 31, wid = tid >> 5;

    const int e  = blockIdx.z;
    const int mb = blockIdx.y;           // 0..31
    const int nb = blockIdx.x;           // 0..15

    const int8_t* hiB = Ah + (((size_t)(e * 32 + mb) * 16) << 14);
    const int8_t* loB = Al + (((size_t)(e * 32 + mb) * 16) << 14);
    const int8_t* bB  = Bt + (((size_t)(e * 16 + nb) * 16) << 14);

    // ---- mma-warp config (wid 0..7): hi plane, 64x32 tiles ----
    const int grp = lane >> 2;
    const int tg4 = (lane & 3) * 4;
    const int wm = wid >> 2;
    const int wn = wid & 3;
    uint32_t baseA[8], baseB[4];
#pragma unroll
    for (int j = 0; j < 8; j++)
        baseA[j] = (uint32_t)((wm * 64 + j * 8 + grp) * 128 + tg4);
#pragma unroll
    for (int j = 0; j < 4; j++)
        baseB[j] = (uint32_t)((wn * 32 + j * 8 + grp) * 128 + tg4);

    // ---- dp4a-warp config (wid 8..15): lo plane, 32x64 tiles ----
    const int dwid = wid - 8;
    const int wtr = dwid >> 1;
    const int wtc = dwid & 1;
    const int lg = lane & 3;
    const int lh = lane >> 2;
    const uint32_t dpA0 = (uint32_t)((wtr * 32 + lg) * 128);
    const uint32_t dpB0 = (uint32_t)((wtc * 64 + lh) * 128);

    int acc_h[4][4][4];
    int acc_lo[8][8];
    if (wid < 8) {
#pragma unroll
        for (int a = 0; a < 4; a++)
#pragma unroll
            for (int b = 0; b < 4; b++)
#pragma unroll
                for (int c = 0; c < 4; c++) acc_h[a][b][c] = 0;
    } else {
#pragma unroll
        for (int a = 0; a < 8; a++)
#pragma unroll
            for (int b = 0; b < 8; b++) acc_lo[a][b] = 0;
    }

    if (tid == 0) {
#pragma unroll
        for (int s = 0; s < NSTAGE; s++) MBARRIER_INIT(mb0 + 8 * s, 1);
    }
    __syncthreads();

    if (tid == 0) {
#pragma unroll
        for (int p = 0; p < NSTAGE; p++) {
            const uint32_t st = sbase + p * STAGE;
            MBARRIER_EXPECT_TX(mb0 + 8 * p, STAGE);
            CP_BULK(st,             hiB + ((size_t)p << 14), PLANE, mb0 + 8 * p);
            CP_BULK(st + PLANE,     loB + ((size_t)p << 14), PLANE, mb0 + 8 * p);
            CP_BULK(st + 2 * PLANE, bB  + ((size_t)p << 14), PLANE, mb0 + 8 * p);
        }
    }

#pragma unroll 1
    for (int i = 0; i < NKIT; i++) {
        const int s = i & 3;
        MBARRIER_WAIT_PARITY(mb0 + 8 * s, (i >> 2) & 1);

        const char* stA = sm + s * STAGE;
        const char* stL = stA + PLANE;
        const char* stB = stA + 2 * PLANE;

        if (wid < 8) {
            // ================= tensor pipe: hi plane =================
#pragma unroll
            for (int ks = 0; ks < 4; ks++) {
                const uint32_t xa = (uint32_t)((((2 * ks) ^ grp) & 7) << 4);
                const uint32_t xb = (uint32_t)((((2 * ks + 1) ^ grp) & 7) << 4);

                uint32_t bf[4][2];
#pragma unroll
                for (int nt = 0; nt < 4; nt++) {
                    bf[nt][0] = *(const uint32_t*)(stB + baseB[nt] + xa);
                    bf[nt][1] = *(const uint32_t*)(stB + baseB[nt] + xb);
                }
#pragma unroll
                for (int mt = 0; mt < 4; mt++) {
                    uint32_t ah[4];
                    ah[0] = *(const uint32_t*)(stA + baseA[2 * mt]     + xa);
                    ah[1] = *(const uint32_t*)(stA + baseA[2 * mt + 1] + xa);
                    ah[2] = *(const uint32_t*)(stA + baseA[2 * mt]     + xb);
                    ah[3] = *(const uint32_t*)(stA + baseA[2 * mt + 1] + xb);
#pragma unroll
                    for (int nt = 0; nt < 4; nt++) {
                        imma(acc_h[mt][nt], ah, bf[nt]);
                    }
                }
            }
        } else {
            // ================= integer pipe: lo plane =================
#pragma unroll 2
            for (int kb = 0; kb < BK; kb += 16) {
                const uint32_t cA0 =
                    (uint32_t)(((((kb >> 4)) ^ lg) & 7) << 4);
                const uint32_t cA1 = cA0 ^ 64u;
                const uint32_t cB =
                    (uint32_t)(((((kb >> 4)) ^ lh) & 7) << 4);
                int4 bv[8];
#pragma unroll
                for (int j2 = 0; j2 < 8; j2++) {
                    bv[j2] = *(const int4*)(stB + dpB0
                                            + (uint32_t)(j2 * 1024) + cB);
                }
#pragma unroll
                for (int j = 0; j < 8; j++) {
                    const int4 a = *(const int4*)(stL + dpA0
                                     + (uint32_t)(j * 512)
                                     + ((j & 1) ? cA1 : cA0));
#pragma unroll
                    for (int j2 = 0; j2 < 8; j2++) {
                        acc_lo[j][j2] =
                            dp4a_(a.x, bv[j2].x,
                            dp4a_(a.y, bv[j2].y,
                            dp4a_(a.z, bv[j2].z,
                            dp4a_(a.w, bv[j2].w, acc_lo[j][j2]))));
                    }
                }
            }
        }
        __syncthreads();

        if (tid == 0 && i + NSTAGE < NKIT) {
            const int kn = i + NSTAGE;
            const uint32_t st = sbase + s * STAGE;
            MBARRIER_EXPECT_TX(mb0 + 8 * s, STAGE);
            CP_BULK(st,             hiB + ((size_t)kn << 14), PLANE, mb0 + 8 * s);
            CP_BULK(st + PLANE,     loB + ((size_t)kn << 14), PLANE, mb0 + 8 * s);
            CP_BULK(st + 2 * PLANE, bB  + ((size_t)kn << 14), PLANE, mb0 + 8 * s);
        }
    }

    // ---------------- epilogue ----------------
    __syncthreads();

    int* xch = (int*)sm;                // 128x128 int32 in stage mem
    if (wid >= 8) {
#pragma unroll
        for (int j = 0; j < 8; j++)
#pragma unroll
            for (int j2 = 0; j2 < 8; j2++) {
                const int r = wtr * 32 + lg + 4 * j;
                const int c = wtc * 64 + lh + 8 * j2;
                xch[r * 128 + c] = acc_lo[j][j2];
            }
    }
    __syncthreads();

    if (wid < 8) {
        const float* rsp = rs + (size_t)e * TT + mb * BM;
        const float* csp = cs + (size_t)e * HH + nb * BN;
        float* Cg = C + ((size_t)e * TT + mb * BM) * HH + nb * BN;

#pragma unroll
        for (int mt = 0; mt < 4; mt++) {
            const int rA = wm * 64 + mt * 16 + grp;
            const float sr0 = rsp[rA];
            const float sr1 = rsp[rA + 8];
#pragma unroll
            for (int nt = 0; nt < 4; nt++) {
                const int cn = wn * 32 + nt * 8 + (lane & 3) * 2;
                const float sc0 = csp[cn];
                const float sc1 = csp[cn + 1];
                const int* hh = acc_h[mt][nt];
                const int2 l0 = *(const int2*)(xch + rA * 128 + cn);
                const int2 l1 = *(const int2*)(xch + (rA + 8) * 128 + cn);
                float2 r0, r1;
                r0.x = fmaf(256.0f, (float)hh[0], (float)l0.x) * (sr0 * sc0);
                r0.y = fmaf(256.0f, (float)hh[1], (float)l0.y) * (sr0 * sc1);
                r1.x = fmaf(256.0f, (float)hh[2], (float)l1.x) * (sr1 * sc0);
                r1.y = fmaf(256.0f, (float)hh[3], (float)l1.y) * (sr1 * sc1);
                *(float2*)(Cg + (size_t)rA * HH + cn)       = r0;
                *(float2*)(Cg + (size_t)(rA + 8) * HH + cn) = r1;
            }
        }
    }
}

// -------------------- launcher --------------------------------------------
extern "C" void kernel_launch(void* const* d_in, const int* in_sizes, int n_in,
                              void* d_out, int out_size) {
    const float* x   = (const float*)d_in[0];
    const int*   w1q = (const int*)d_in[1];
    const float* w1s = (const float*)d_in[2];
    const int*   w2q = (const int*)d_in[3];
    const float* w2s = (const float*)d_in[4];
    float*       out = (float*)d_out;

    void *pw1t, *pw2t, *pahi, *palo, *prs, *ph;
    cudaGetSymbolAddress(&pw1t, g_w1t);
    cudaGetSymbolAddress(&pw2t, g_w2t);
    cudaGetSymbolAddress(&pahi, g_ahi);
    cudaGetSymbolAddress(&palo, g_alo);
    cudaGetSymbolAddress(&prs,  g_rs);
    cudaGetSymbolAddress(&ph,   g_h);

    dim3 cb(32, 8), cg(HH / 32, HH / 32, EE);
    convw_kernel<<<cg, cb>>>(w1q, (int8_t*)pw1t);
    convw_kernel<<<cg, cb>>>(w2q, (int8_t*)pw2t);

    quant_kernel<<<EE * TT, 128>>>(x, (int8_t*)pahi, (int8_t*)palo,
                                   (float*)prs);

    cudaFuncSetAttribute(imma_gemm,
                         cudaFuncAttributeMaxDynamicSharedMemorySize, DYNSMEM);
    dim3 gg(HH / BN, TT / BM, EE);   // (16, 32, 8)

    imma_gemm<<<gg, 512, DYNSMEM>>>((const int8_t*)pahi, (const int8_t*)palo,
                                    (const float*)prs, (const int8_t*)pw1t,
                                    w1s, (float*)ph);

    quant_kernel<<<EE * TT, 128>>>((const float*)ph, (int8_t*)pahi,
                                   (int8_t*)palo, (float*)prs);

    imma_gemm<<<gg, 512, DYNSMEM>>>((const int8_t*)pahi, (const int8_t*)palo,
                                    (const float*)prs, (const int8_t*)pw2t,
                                    w2s, out);
}